// round 1
// baseline (speedup 1.0000x reference)
#include <cuda_runtime.h>
#include <math.h>

#define NN 100000
#define EE 3200000

// ---------------- scratch (device globals; no runtime allocation) ----------------
__device__ float g_deg[NN];
__device__ float g_dis[NN];
__device__ int   g_cnt[NN];
__device__ int   g_off[NN];
__device__ int   g_cur[NN];
__device__ unsigned long long g_edge[EE];   // packed {norm:f32 (hi), src:i32 (lo)}
__device__ float g_Ax[NN];
__device__ __align__(16) float g_fa[NN*48]; // conv1 features, ping
__device__ __align__(16) float g_fb[NN*48]; // conv1 features, pong
__device__ __align__(16) float g_h[NN*16];  // conv1 output after BN+relu
__device__ __align__(16) float g_oa[NN*4];  // conv2 state ping (3 used + pad)
__device__ __align__(16) float g_ob[NN*4];  // conv2 state pong
__device__ __align__(16) float g_root2[NN*4];
__device__ int   g_bsum[128];

// ---------------- gcn_norm + CSR build ----------------
__global__ void k_zero() {
    int i = blockIdx.x*blockDim.x + threadIdx.x;
    if (i < NN) { g_deg[i] = 0.f; g_cnt[i] = 0; }
}

__global__ void k_deg(const int* __restrict__ col, const float* __restrict__ ew) {
    int e = blockIdx.x*blockDim.x + threadIdx.x;
    if (e < EE) {
        int c = col[e];
        atomicAdd(&g_deg[c], ew[e]);
        atomicAdd(&g_cnt[c], 1);
    }
}

__global__ void k_dis() {
    int i = blockIdx.x*blockDim.x + threadIdx.x;
    if (i < NN) {
        float d = g_deg[i];
        g_dis[i] = d > 0.f ? rsqrtf(fmaxf(d, 1e-12f)) : 0.f;
    }
}

__global__ void k_scanA() {
    __shared__ int s[1024];
    int i = blockIdx.x*1024 + threadIdx.x;
    int v = (i < NN) ? g_cnt[i] : 0;
    s[threadIdx.x] = v;
    __syncthreads();
    for (int off = 1; off < 1024; off <<= 1) {
        int t = (threadIdx.x >= off) ? s[threadIdx.x - off] : 0;
        __syncthreads();
        s[threadIdx.x] += t;
        __syncthreads();
    }
    if (i < NN) g_off[i] = s[threadIdx.x] - v;   // exclusive within block
    if (threadIdx.x == 1023) g_bsum[blockIdx.x] = s[1023];
}

__global__ void k_scanB(int nb) {
    if (threadIdx.x == 0 && blockIdx.x == 0) {
        int run = 0;
        for (int j = 0; j < nb; j++) { int t = g_bsum[j]; g_bsum[j] = run; run += t; }
    }
}

__global__ void k_scanC() {
    int i = blockIdx.x*blockDim.x + threadIdx.x;
    if (i < NN) {
        int o = g_off[i] + g_bsum[i >> 10];
        g_off[i] = o;
        g_cur[i] = o;
    }
}

__global__ void k_scatter(const int* __restrict__ row, const int* __restrict__ colv,
                          const float* __restrict__ ew) {
    int e = blockIdx.x*blockDim.x + threadIdx.x;
    if (e < EE) {
        int r = row[e], c = colv[e];
        float nm = g_dis[r] * ew[e] * g_dis[c];
        int p = atomicAdd(&g_cur[c], 1);
        unsigned long long pk =
            (((unsigned long long)(unsigned int)__float_as_int(nm)) << 32) | (unsigned int)r;
        g_edge[p] = pk;
    }
}

// ---------------- conv1 ----------------
// Ax[n] = sum over in-edges of norm * x[src]   (rank-1 first propagation)
__global__ void k_ax(const float* __restrict__ x) {
    int n = blockIdx.x*blockDim.x + threadIdx.x;
    if (n >= NN) return;
    int st = g_off[n], cn = g_cnt[n];
    float s = 0.f;
    for (int j = 0; j < cn; j++) {
        unsigned long long pk = g_edge[st + j];
        int src = (int)(pk & 0xffffffffu);
        float nm = __int_as_float((int)(pk >> 32));
        s += nm * __ldg(&x[src]);
    }
    g_Ax[n] = s;
}

// feat layout per node: 12 float4 chunks; chunk index = c*3 + k holds
// features [4c, 4c+3] of stack k. (keeps the 3 stack-lanes of one node in 1 line)
__global__ void k_feat0(const float* __restrict__ x, const float* __restrict__ iw,
                        const float* __restrict__ rw, const float* __restrict__ bs) {
    int t = blockIdx.x*blockDim.x + threadIdx.x;
    if (t >= NN*3) return;
    int n = t/3, k = t - n*3;
    float ax = g_Ax[n], xv = x[n];
    float4* dst = (float4*)(g_fa + n*48);
    #pragma unroll
    for (int c = 0; c < 4; c++) {
        float4 o;
        float* po = (float*)&o;
        #pragma unroll
        for (int i = 0; i < 4; i++) {
            int f = c*4 + i;
            po[i] = fmaxf(ax*__ldg(&iw[k*16+f]) + xv*__ldg(&rw[k*16+f]) + __ldg(&bs[k*16+f]), 0.f);
        }
        dst[c*3 + k] = o;
    }
}

// one thread per (node, stack): pull-SpMM + fused 16x16 matmul + root + relu
__global__ void __launch_bounds__(384)
k_iter1(int srcIsB, const float* __restrict__ x, const float* __restrict__ w,
        const float* __restrict__ rw, const float* __restrict__ bs) {
    __shared__ float wsh[768];
    __shared__ float rwsh[48], bsh[48];
    for (int i = threadIdx.x; i < 768; i += 384) wsh[i] = w[i];
    if (threadIdx.x < 48) { rwsh[threadIdx.x] = rw[threadIdx.x]; bsh[threadIdx.x] = bs[threadIdx.x]; }
    __syncthreads();

    int t = blockIdx.x*384 + threadIdx.x;
    if (t >= NN*3) return;
    int n = t/3, k = t - n*3;
    int st = g_off[n], cn = g_cnt[n];
    const float4* F = (const float4*)(srcIsB ? g_fb : g_fa);
    float*        D = srcIsB ? g_fa : g_fb;

    float acc[16];
    #pragma unroll
    for (int i = 0; i < 16; i++) acc[i] = 0.f;

    int j = 0;
    for (; j + 1 < cn; j += 2) {
        unsigned long long p0 = g_edge[st+j], p1 = g_edge[st+j+1];
        int s0 = (int)(p0 & 0xffffffffu), s1 = (int)(p1 & 0xffffffffu);
        float m0 = __int_as_float((int)(p0 >> 32));
        float m1 = __int_as_float((int)(p1 >> 32));
        int b0 = s0*12 + k, b1 = s1*12 + k;
        float4 a0 = F[b0], a1 = F[b0+3], a2 = F[b0+6], a3 = F[b0+9];
        float4 c0 = F[b1], c1 = F[b1+3], c2 = F[b1+6], c3 = F[b1+9];
        acc[0]+=m0*a0.x; acc[1]+=m0*a0.y; acc[2]+=m0*a0.z; acc[3]+=m0*a0.w;
        acc[4]+=m0*a1.x; acc[5]+=m0*a1.y; acc[6]+=m0*a1.z; acc[7]+=m0*a1.w;
        acc[8]+=m0*a2.x; acc[9]+=m0*a2.y; acc[10]+=m0*a2.z; acc[11]+=m0*a2.w;
        acc[12]+=m0*a3.x; acc[13]+=m0*a3.y; acc[14]+=m0*a3.z; acc[15]+=m0*a3.w;
        acc[0]+=m1*c0.x; acc[1]+=m1*c0.y; acc[2]+=m1*c0.z; acc[3]+=m1*c0.w;
        acc[4]+=m1*c1.x; acc[5]+=m1*c1.y; acc[6]+=m1*c1.z; acc[7]+=m1*c1.w;
        acc[8]+=m1*c2.x; acc[9]+=m1*c2.y; acc[10]+=m1*c2.z; acc[11]+=m1*c2.w;
        acc[12]+=m1*c3.x; acc[13]+=m1*c3.y; acc[14]+=m1*c3.z; acc[15]+=m1*c3.w;
    }
    if (j < cn) {
        unsigned long long p0 = g_edge[st+j];
        int s0 = (int)(p0 & 0xffffffffu);
        float m0 = __int_as_float((int)(p0 >> 32));
        int b0 = s0*12 + k;
        float4 a0 = F[b0], a1 = F[b0+3], a2 = F[b0+6], a3 = F[b0+9];
        acc[0]+=m0*a0.x; acc[1]+=m0*a0.y; acc[2]+=m0*a0.z; acc[3]+=m0*a0.w;
        acc[4]+=m0*a1.x; acc[5]+=m0*a1.y; acc[6]+=m0*a1.z; acc[7]+=m0*a1.w;
        acc[8]+=m0*a2.x; acc[9]+=m0*a2.y; acc[10]+=m0*a2.z; acc[11]+=m0*a2.w;
        acc[12]+=m0*a3.x; acc[13]+=m0*a3.y; acc[14]+=m0*a3.z; acc[15]+=m0*a3.w;
    }

    // y = acc * W[k]  (A(out)·w == A(out·w)), then + root, relu
    float xv = x[n];
    const float* wk = wsh + k*256;
    float4* dst = (float4*)(D + n*48);
    #pragma unroll
    for (int c = 0; c < 4; c++) {
        float4 o;
        float* po = (float*)&o;
        #pragma unroll
        for (int i = 0; i < 4; i++) {
            int oo = c*4 + i;
            float y = 0.f;
            #pragma unroll
            for (int f = 0; f < 16; f++) y += acc[f] * wk[f*16 + oo];
            po[i] = fmaxf(y + xv*rwsh[k*16+oo] + bsh[k*16+oo], 0.f);
        }
        dst[c*3 + k] = o;
    }
}

// mean over stacks + BatchNorm(eval) + relu  (conv1 final state is in g_fb)
__global__ void k_h(const float* __restrict__ gamma, const float* __restrict__ beta,
                    const float* __restrict__ mean, const float* __restrict__ var) {
    int n = blockIdx.x*blockDim.x + threadIdx.x;
    if (n >= NN) return;
    const float4* F = (const float4*)(g_fb + n*48);
    float4* Ho = (float4*)(g_h + n*16);
    #pragma unroll
    for (int c = 0; c < 4; c++) {
        float4 a = F[c*3+0], b = F[c*3+1], d = F[c*3+2];
        float* pa = (float*)&a; float* pb = (float*)&b; float* pd = (float*)&d;
        float4 o; float* po = (float*)&o;
        #pragma unroll
        for (int i = 0; i < 4; i++) {
            int f = c*4 + i;
            float m = (pa[i] + pb[i] + pd[i]) * (1.f/3.f);
            float sc = __ldg(&gamma[f]) * rsqrtf(__ldg(&var[f]) + 1e-5f);
            po[i] = fmaxf((m - __ldg(&mean[f]))*sc + __ldg(&beta[f]), 0.f);
        }
        Ho[c] = o;
    }
}

// ---------------- conv2 ----------------
__global__ void k_prep2(const float* __restrict__ iw2, const float* __restrict__ rw2,
                        const float* __restrict__ b2) {
    int n = blockIdx.x*blockDim.x + threadIdx.x;
    if (n >= NN) return;
    float h[16];
    const float4* Hp = (const float4*)(g_h + n*16);
    #pragma unroll
    for (int c = 0; c < 4; c++) {
        float4 v = Hp[c];
        h[c*4+0]=v.x; h[c*4+1]=v.y; h[c*4+2]=v.z; h[c*4+3]=v.w;
    }
    float o[3] = {0,0,0}, r[3] = {0,0,0};
    #pragma unroll
    for (int k = 0; k < 3; k++) {
        #pragma unroll
        for (int f = 0; f < 16; f++) {
            o[k] += h[f] * __ldg(&iw2[k*16+f]);
            r[k] += h[f] * __ldg(&rw2[k*16+f]);
        }
        r[k] += __ldg(&b2[k]);
    }
    float4 ov; ov.x=o[0]; ov.y=o[1]; ov.z=o[2]; ov.w=0.f;
    float4 rv; rv.x=r[0]; rv.y=r[1]; rv.z=r[2]; rv.w=0.f;
    ((float4*)g_oa)[n] = ov;
    ((float4*)g_root2)[n] = rv;
}

__global__ void k_iter2(int srcIsB, const float* __restrict__ w2, int applyW) {
    int n = blockIdx.x*blockDim.x + threadIdx.x;
    if (n >= NN) return;
    int st = g_off[n], cn = g_cnt[n];
    const float4* S = (const float4*)(srcIsB ? g_ob : g_oa);
    float4*       D = (float4*)(srcIsB ? g_oa : g_ob);
    float a0 = 0.f, a1 = 0.f, a2 = 0.f;
    int j = 0;
    for (; j + 1 < cn; j += 2) {
        unsigned long long p0 = g_edge[st+j], p1 = g_edge[st+j+1];
        int s0 = (int)(p0 & 0xffffffffu), s1 = (int)(p1 & 0xffffffffu);
        float m0 = __int_as_float((int)(p0 >> 32));
        float m1 = __int_as_float((int)(p1 >> 32));
        float4 v0 = S[s0], v1 = S[s1];
        a0 += m0*v0.x; a1 += m0*v0.y; a2 += m0*v0.z;
        a0 += m1*v1.x; a1 += m1*v1.y; a2 += m1*v1.z;
    }
    if (j < cn) {
        unsigned long long p0 = g_edge[st+j];
        int s0 = (int)(p0 & 0xffffffffu);
        float m0 = __int_as_float((int)(p0 >> 32));
        float4 v0 = S[s0];
        a0 += m0*v0.x; a1 += m0*v0.y; a2 += m0*v0.z;
    }
    if (applyW) {
        a0 *= __ldg(&w2[0]); a1 *= __ldg(&w2[1]); a2 *= __ldg(&w2[2]);
    }
    float4 rt = ((const float4*)g_root2)[n];
    float4 o; o.x = a0 + rt.x; o.y = a1 + rt.y; o.z = a2 + rt.z; o.w = 0.f;
    D[n] = o;
}

__global__ void k_final(float* __restrict__ out) {
    int n = blockIdx.x*blockDim.x + threadIdx.x;
    if (n >= NN) return;
    float4 v = ((const float4*)g_oa)[n];
    float s = (v.x + v.y + v.z) * (1.f/3.f);
    out[n] = 1.f / (1.f + expf(-s));
}

// ---------------- driver ----------------
extern "C" void kernel_launch(void* const* d_in, const int* in_sizes, int n_in,
                              void* d_out, int out_size) {
    const float* x    = (const float*)d_in[0];
    const int*   ei   = (const int*)  d_in[1];
    const float* ew   = (const float*)d_in[2];
    const float* c1iw = (const float*)d_in[3];
    const float* c1w  = (const float*)d_in[4];
    const float* c1rw = (const float*)d_in[5];
    const float* c1b  = (const float*)d_in[6];
    const float* bng  = (const float*)d_in[7];
    const float* bnb  = (const float*)d_in[8];
    const float* bnm  = (const float*)d_in[9];
    const float* bnv  = (const float*)d_in[10];
    const float* c2iw = (const float*)d_in[11];
    const float* c2w  = (const float*)d_in[12];
    const float* c2rw = (const float*)d_in[13];
    const float* c2b  = (const float*)d_in[14];
    float* out = (float*)d_out;

    const int* row = ei;
    const int* col = ei + EE;

    const int NG  = (NN + 255) / 256;
    const int EG  = (EE + 255) / 256;
    const int NB  = (NN + 1023) / 1024;
    const int TG3 = (NN*3 + 383) / 384;

    // gcn_norm + CSR build
    k_zero<<<NG, 256>>>();
    k_deg<<<EG, 256>>>(col, ew);
    k_dis<<<NG, 256>>>();
    k_scanA<<<NB, 1024>>>();
    k_scanB<<<1, 32>>>(NB);
    k_scanC<<<NG, 256>>>();
    k_scatter<<<EG, 256>>>(row, col, ew);

    // conv1: rank-1 first propagation, then 3 full SpMM iterations (fused W)
    k_ax<<<NG, 256>>>(x);
    k_feat0<<<TG3, 384>>>(x, c1iw, c1rw, c1b);
    k_iter1<<<TG3, 384>>>(0, x, c1w, c1rw, c1b);  // fa -> fb
    k_iter1<<<TG3, 384>>>(1, x, c1w, c1rw, c1b);  // fb -> fa
    k_iter1<<<TG3, 384>>>(0, x, c1w, c1rw, c1b);  // fa -> fb

    // mean over stacks + BN + relu
    k_h<<<NG, 256>>>(bng, bnb, bnm, bnv);

    // conv2 (Fout=1, padded float4 state)
    k_prep2<<<NG, 256>>>(c2iw, c2rw, c2b);
    k_iter2<<<NG, 256>>>(0, c2w, 0);  // oa -> ob, t=0 (no w)
    k_iter2<<<NG, 256>>>(1, c2w, 1);  // ob -> oa
    k_iter2<<<NG, 256>>>(0, c2w, 1);  // oa -> ob
    k_iter2<<<NG, 256>>>(1, c2w, 1);  // ob -> oa (final in oa)

    k_final<<<NG, 256>>>(out);
}

// round 3
// speedup vs baseline: 1.0111x; 1.0111x over previous
#include <cuda_runtime.h>
#include <math.h>

#define NN 100000
#define EE 3200000

// ---------------- scratch (device globals; no runtime allocation) ----------------
__device__ float g_deg[NN];
__device__ float g_dis[NN];
__device__ int   g_cnt[NN];
__device__ int   g_off[NN];
__device__ int   g_cur[NN];
__device__ unsigned long long g_edge[EE];   // packed {norm:f32 (hi), src:i32 (lo)}
__device__ float g_Ax[NN];
__device__ __align__(16) float g_fa[NN*48]; // conv1 features, ping
__device__ __align__(16) float g_fb[NN*48]; // conv1 features, pong
__device__ __align__(16) float g_oa[NN*4];  // conv2 state ping (3 used + pad)
__device__ __align__(16) float g_ob[NN*4];  // conv2 state pong
__device__ __align__(16) float g_root2[NN*4];
__device__ int   g_bsum[128];

// ---------------- gcn_norm + CSR build ----------------
__global__ void k_zero() {
    int i = blockIdx.x*blockDim.x + threadIdx.x;
    if (i < NN) { g_deg[i] = 0.f; g_cnt[i] = 0; }
}

__global__ void k_deg(const int* __restrict__ col, const float* __restrict__ ew) {
    int e = blockIdx.x*blockDim.x + threadIdx.x;
    if (e < EE) {
        int c = col[e];
        atomicAdd(&g_deg[c], ew[e]);
        atomicAdd(&g_cnt[c], 1);
    }
}

// block scan over counts; also computes dis (fused elementwise)
__global__ void k_scanA() {
    __shared__ int s[1024];
    int i = blockIdx.x*1024 + threadIdx.x;
    if (i < NN) {
        float d = g_deg[i];
        g_dis[i] = d > 0.f ? rsqrtf(fmaxf(d, 1e-12f)) : 0.f;
    }
    int v = (i < NN) ? g_cnt[i] : 0;
    s[threadIdx.x] = v;
    __syncthreads();
    for (int off = 1; off < 1024; off <<= 1) {
        int t = (threadIdx.x >= off) ? s[threadIdx.x - off] : 0;
        __syncthreads();
        s[threadIdx.x] += t;
        __syncthreads();
    }
    if (i < NN) g_off[i] = s[threadIdx.x] - v;   // exclusive within block
    if (threadIdx.x == 1023) g_bsum[blockIdx.x] = s[1023];
}

__global__ void k_scanB(int nb) {
    if (threadIdx.x == 0 && blockIdx.x == 0) {
        int run = 0;
        for (int j = 0; j < nb; j++) { int t = g_bsum[j]; g_bsum[j] = run; run += t; }
    }
}

__global__ void k_scanC() {
    int i = blockIdx.x*blockDim.x + threadIdx.x;
    if (i < NN) {
        int o = g_off[i] + g_bsum[i >> 10];
        g_off[i] = o;
        g_cur[i] = o;
    }
}

__global__ void k_scatter(const int* __restrict__ row, const int* __restrict__ colv,
                          const float* __restrict__ ew) {
    int e = blockIdx.x*blockDim.x + threadIdx.x;
    if (e < EE) {
        int r = row[e], c = colv[e];
        float nm = g_dis[r] * ew[e] * g_dis[c];
        int p = atomicAdd(&g_cur[c], 1);
        unsigned long long pk =
            (((unsigned long long)(unsigned int)__float_as_int(nm)) << 32) | (unsigned int)r;
        g_edge[p] = pk;
    }
}

// ---------------- conv1 ----------------
// Ax[n] = sum over in-edges of norm * x[src]; 2 threads per node (half-split)
__global__ void k_ax2(const float* __restrict__ x) {
    __shared__ float part[256];
    int tid = threadIdx.x;
    int nl = tid >> 1, h = tid & 1;
    int n = blockIdx.x*128 + nl;
    float s = 0.f;
    if (n < NN) {
        int st = g_off[n], cn = g_cnt[n];
        int c0 = (cn + 1) >> 1;
        int jb = st + (h ? c0 : 0);
        int je = st + (h ? cn : c0);
        for (int j = jb; j < je; j++) {
            unsigned long long pk = g_edge[j];
            s += __int_as_float((int)(pk >> 32)) * __ldg(&x[(int)(pk & 0xffffffffu)]);
        }
    }
    part[tid] = s;
    __syncthreads();
    if (h == 0 && n < NN) g_Ax[n] = s + part[tid + 1];
}

// feat layout per node: 12 float4 chunks; chunk index = c*3 + k holds
// features [4c, 4c+3] of stack k.
__global__ void k_feat0(const float* __restrict__ x, const float* __restrict__ iw,
                        const float* __restrict__ rw, const float* __restrict__ bs) {
    int t = blockIdx.x*blockDim.x + threadIdx.x;
    if (t >= NN*3) return;
    int n = t/3, k = t - n*3;
    float ax = g_Ax[n], xv = x[n];
    float4* dst = (float4*)(g_fa + n*48);
    #pragma unroll
    for (int c = 0; c < 4; c++) {
        float4 o;
        float* po = (float*)&o;
        #pragma unroll
        for (int i = 0; i < 4; i++) {
            int f = c*4 + i;
            po[i] = fmaxf(ax*__ldg(&iw[k*16+f]) + xv*__ldg(&rw[k*16+f]) + __ldg(&bs[k*16+f]), 0.f);
        }
        dst[c*3 + k] = o;
    }
}

// 6 threads per node: (half h in {0,1}) x (stack k in {0,1,2}).
// Each accumulates its half of the edge list for its stack; partials combined
// through smem; the two half-threads split the 16x16 epilogue matmul.
// Block = 192 threads = 32 nodes. Grid = 3125 (exact: 32*3125 = 100000).
__global__ void __launch_bounds__(192)
k_iter1(int srcIsB, const float* __restrict__ x, const float* __restrict__ w,
        const float* __restrict__ rw, const float* __restrict__ bs) {
    __shared__ float wsh[768];
    __shared__ float rwsh[48], bsh[48];
    __shared__ float part[192][17];
    for (int i = threadIdx.x; i < 768; i += 192) wsh[i] = w[i];
    if (threadIdx.x < 48) { rwsh[threadIdx.x] = rw[threadIdx.x]; bsh[threadIdx.x] = bs[threadIdx.x]; }
    __syncthreads();

    int tid = threadIdx.x;
    int nl  = tid / 6;
    int sub = tid - nl*6;
    int h = sub / 3, k = sub - h*3;
    int n = blockIdx.x*32 + nl;            // grid is exact, n < NN always
    int st = g_off[n], cn = g_cnt[n];
    int c0 = (cn + 1) >> 1;
    int jb = st + (h ? c0 : 0);
    int je = st + (h ? cn : c0);
    const float4* F = (const float4*)(srcIsB ? g_fb : g_fa);
    float*        D = srcIsB ? g_fa : g_fb;

    float acc[16];
    #pragma unroll
    for (int i = 0; i < 16; i++) acc[i] = 0.f;

    int j = jb;
    for (; j + 1 < je; j += 2) {
        unsigned long long p0 = g_edge[j], p1 = g_edge[j+1];
        int s0 = (int)(p0 & 0xffffffffu), s1 = (int)(p1 & 0xffffffffu);
        float m0 = __int_as_float((int)(p0 >> 32));
        float m1 = __int_as_float((int)(p1 >> 32));
        int b0 = s0*12 + k, b1 = s1*12 + k;
        float4 a0 = __ldg(&F[b0]), a1 = __ldg(&F[b0+3]), a2 = __ldg(&F[b0+6]), a3 = __ldg(&F[b0+9]);
        float4 d0 = __ldg(&F[b1]), d1 = __ldg(&F[b1+3]), d2 = __ldg(&F[b1+6]), d3 = __ldg(&F[b1+9]);
        acc[0]+=m0*a0.x; acc[1]+=m0*a0.y; acc[2]+=m0*a0.z; acc[3]+=m0*a0.w;
        acc[4]+=m0*a1.x; acc[5]+=m0*a1.y; acc[6]+=m0*a1.z; acc[7]+=m0*a1.w;
        acc[8]+=m0*a2.x; acc[9]+=m0*a2.y; acc[10]+=m0*a2.z; acc[11]+=m0*a2.w;
        acc[12]+=m0*a3.x; acc[13]+=m0*a3.y; acc[14]+=m0*a3.z; acc[15]+=m0*a3.w;
        acc[0]+=m1*d0.x; acc[1]+=m1*d0.y; acc[2]+=m1*d0.z; acc[3]+=m1*d0.w;
        acc[4]+=m1*d1.x; acc[5]+=m1*d1.y; acc[6]+=m1*d1.z; acc[7]+=m1*d1.w;
        acc[8]+=m1*d2.x; acc[9]+=m1*d2.y; acc[10]+=m1*d2.z; acc[11]+=m1*d2.w;
        acc[12]+=m1*d3.x; acc[13]+=m1*d3.y; acc[14]+=m1*d3.z; acc[15]+=m1*d3.w;
    }
    if (j < je) {
        unsigned long long p0 = g_edge[j];
        int s0 = (int)(p0 & 0xffffffffu);
        float m0 = __int_as_float((int)(p0 >> 32));
        int b0 = s0*12 + k;
        float4 a0 = __ldg(&F[b0]), a1 = __ldg(&F[b0+3]), a2 = __ldg(&F[b0+6]), a3 = __ldg(&F[b0+9]);
        acc[0]+=m0*a0.x; acc[1]+=m0*a0.y; acc[2]+=m0*a0.z; acc[3]+=m0*a0.w;
        acc[4]+=m0*a1.x; acc[5]+=m0*a1.y; acc[6]+=m0*a1.z; acc[7]+=m0*a1.w;
        acc[8]+=m0*a2.x; acc[9]+=m0*a2.y; acc[10]+=m0*a2.z; acc[11]+=m0*a2.w;
        acc[12]+=m0*a3.x; acc[13]+=m0*a3.y; acc[14]+=m0*a3.z; acc[15]+=m0*a3.w;
    }

    #pragma unroll
    for (int i = 0; i < 16; i++) part[tid][i] = acc[i];
    __syncthreads();

    int base = nl*6;
    float af[16];
    #pragma unroll
    for (int i = 0; i < 16; i++) af[i] = part[base + k][i] + part[base + 3 + k][i];

    // y = af * W[k] (A(out)w == A(out w)), + root + relu; halves split chunks
    float xv = x[n];
    const float* wk = wsh + k*256;
    float4* dst = (float4*)(D + n*48);
    #pragma unroll
    for (int cc = 0; cc < 2; cc++) {
        int c = h*2 + cc;
        float4 o;
        float* po = (float*)&o;
        #pragma unroll
        for (int i = 0; i < 4; i++) {
            int oo = c*4 + i;
            float y = 0.f;
            #pragma unroll
            for (int f = 0; f < 16; f++) y += af[f] * wk[f*16 + oo];
            po[i] = fmaxf(y + xv*rwsh[k*16+oo] + bsh[k*16+oo], 0.f);
        }
        dst[c*3 + k] = o;
    }
}

// mean over stacks + BN(eval) + relu + conv2 input/root transforms (fused)
__global__ void k_hprep(const float* __restrict__ gamma, const float* __restrict__ beta,
                        const float* __restrict__ mean, const float* __restrict__ var,
                        const float* __restrict__ iw2, const float* __restrict__ rw2,
                        const float* __restrict__ b2) {
    int n = blockIdx.x*blockDim.x + threadIdx.x;
    if (n >= NN) return;
    const float4* F = (const float4*)(g_fb + n*48);
    float hv[16];
    #pragma unroll
    for (int c = 0; c < 4; c++) {
        float4 a = F[c*3+0], b = F[c*3+1], d = F[c*3+2];
        float* pa = (float*)&a; float* pb = (float*)&b; float* pd = (float*)&d;
        #pragma unroll
        for (int i = 0; i < 4; i++) {
            int f = c*4 + i;
            float m = (pa[i] + pb[i] + pd[i]) * (1.f/3.f);
            float sc = __ldg(&gamma[f]) * rsqrtf(__ldg(&var[f]) + 1e-5f);
            hv[f] = fmaxf((m - __ldg(&mean[f]))*sc + __ldg(&beta[f]), 0.f);
        }
    }
    float o[3] = {0,0,0}, r[3] = {0,0,0};
    #pragma unroll
    for (int k = 0; k < 3; k++) {
        #pragma unroll
        for (int f = 0; f < 16; f++) {
            o[k] += hv[f] * __ldg(&iw2[k*16+f]);
            r[k] += hv[f] * __ldg(&rw2[k*16+f]);
        }
        r[k] += __ldg(&b2[k]);
    }
    float4 ov; ov.x=o[0]; ov.y=o[1]; ov.z=o[2]; ov.w=0.f;
    float4 rv; rv.x=r[0]; rv.y=r[1]; rv.z=r[2]; rv.w=0.f;
    ((float4*)g_oa)[n] = ov;
    ((float4*)g_root2)[n] = rv;
}

// conv2 iteration: 2 threads per node (half-split); last call fuses sigmoid
__global__ void k_iter2(int srcIsB, const float* __restrict__ w2, int applyW,
                        float* __restrict__ finalOut) {
    __shared__ float pa[256], pb[256], pc[256];
    int tid = threadIdx.x;
    int nl = tid >> 1, h = tid & 1;
    int n = blockIdx.x*128 + nl;
    float a0 = 0.f, a1 = 0.f, a2 = 0.f;
    const float4* S = (const float4*)(srcIsB ? g_ob : g_oa);
    if (n < NN) {
        int st = g_off[n], cn = g_cnt[n];
        int c0 = (cn + 1) >> 1;
        int jb = st + (h ? c0 : 0);
        int je = st + (h ? cn : c0);
        int j = jb;
        for (; j + 1 < je; j += 2) {
            unsigned long long p0 = g_edge[j], p1 = g_edge[j+1];
            int s0 = (int)(p0 & 0xffffffffu), s1 = (int)(p1 & 0xffffffffu);
            float m0 = __int_as_float((int)(p0 >> 32));
            float m1 = __int_as_float((int)(p1 >> 32));
            float4 v0 = __ldg(&S[s0]), v1 = __ldg(&S[s1]);
            a0 += m0*v0.x; a1 += m0*v0.y; a2 += m0*v0.z;
            a0 += m1*v1.x; a1 += m1*v1.y; a2 += m1*v1.z;
        }
        if (j < je) {
            unsigned long long p0 = g_edge[j];
            int s0 = (int)(p0 & 0xffffffffu);
            float m0 = __int_as_float((int)(p0 >> 32));
            float4 v0 = __ldg(&S[s0]);
            a0 += m0*v0.x; a1 += m0*v0.y; a2 += m0*v0.z;
        }
    }
    pa[tid] = a0; pb[tid] = a1; pc[tid] = a2;
    __syncthreads();
    if (h == 0 && n < NN) {
        a0 += pa[tid+1]; a1 += pb[tid+1]; a2 += pc[tid+1];
        if (applyW) {
            a0 *= __ldg(&w2[0]); a1 *= __ldg(&w2[1]); a2 *= __ldg(&w2[2]);
        }
        float4 rt = ((const float4*)g_root2)[n];
        a0 += rt.x; a1 += rt.y; a2 += rt.z;
        if (finalOut) {
            float s = (a0 + a1 + a2) * (1.f/3.f);
            finalOut[n] = 1.f / (1.f + expf(-s));
        } else {
            float4* Dp = (float4*)(srcIsB ? g_oa : g_ob);
            float4 o; o.x = a0; o.y = a1; o.z = a2; o.w = 0.f;
            Dp[n] = o;
        }
    }
}

// ---------------- driver ----------------
extern "C" void kernel_launch(void* const* d_in, const int* in_sizes, int n_in,
                              void* d_out, int out_size) {
    const float* x    = (const float*)d_in[0];
    const int*   ei   = (const int*)  d_in[1];
    const float* ew   = (const float*)d_in[2];
    const float* c1iw = (const float*)d_in[3];
    const float* c1w  = (const float*)d_in[4];
    const float* c1rw = (const float*)d_in[5];
    const float* c1b  = (const float*)d_in[6];
    const float* bng  = (const float*)d_in[7];
    const float* bnb  = (const float*)d_in[8];
    const float* bnm  = (const float*)d_in[9];
    const float* bnv  = (const float*)d_in[10];
    const float* c2iw = (const float*)d_in[11];
    const float* c2w  = (const float*)d_in[12];
    const float* c2rw = (const float*)d_in[13];
    const float* c2b  = (const float*)d_in[14];
    float* out = (float*)d_out;

    const int* row = ei;
    const int* col = ei + EE;

    const int NG  = (NN + 255) / 256;
    const int EG  = (EE + 255) / 256;
    const int NB  = (NN + 1023) / 1024;
    const int TG3 = (NN*3 + 383) / 384;
    const int HG  = (NN + 127) / 128;     // 2 threads/node, block 256

    // gcn_norm + CSR build
    k_zero<<<NG, 256>>>();
    k_deg<<<EG, 256>>>(col, ew);
    k_scanA<<<NB, 1024>>>();
    k_scanB<<<1, 32>>>(NB);
    k_scanC<<<NG, 256>>>();
    k_scatter<<<EG, 256>>>(row, col, ew);

    // conv1: rank-1 first propagation, then 3 full SpMM iterations (fused W)
    k_ax2<<<HG, 256>>>(x);
    k_feat0<<<TG3, 384>>>(x, c1iw, c1rw, c1b);
    k_iter1<<<3125, 192>>>(0, x, c1w, c1rw, c1b);  // fa -> fb
    k_iter1<<<3125, 192>>>(1, x, c1w, c1rw, c1b);  // fb -> fa
    k_iter1<<<3125, 192>>>(0, x, c1w, c1rw, c1b);  // fa -> fb

    // mean + BN + relu + conv2 input/root (fused)
    k_hprep<<<NG, 256>>>(bng, bnb, bnm, bnv, c2iw, c2rw, c2b);

    // conv2 (Fout=1), last iteration fuses sigmoid -> out
    k_iter2<<<HG, 256>>>(0, c2w, 0, nullptr);  // oa -> ob
    k_iter2<<<HG, 256>>>(1, c2w, 1, nullptr);  // ob -> oa
    k_iter2<<<HG, 256>>>(0, c2w, 1, nullptr);  // oa -> ob
    k_iter2<<<HG, 256>>>(1, c2w, 1, out);      // ob -> sigmoid -> out

    k_final_unused_guard:;
}